// round 3
// baseline (speedup 1.0000x reference)
#include <cuda_runtime.h>
#include <math.h>

#define BB 16
#define NN 512
#define CC 512
#define NS 16
#define CM 64           // CC / S
#define ROWS (BB*NN)    // 8192

// ---------------- scratch (static device globals; no allocation) -------------
__device__ float g_xq[ROWS*CC];
__device__ float g_xk[ROWS*CC];
__device__ float g_xv[ROWS*CC];
__device__ int   g_idx[ROWS*NS];

// ============================ kNN kernel =====================================
// One thread per query point; batch's points + sq-norms cached in smem.
// Arithmetic replicates the reference EXACTLY (ulp-level):
//   sq   = (p0*p0 + p1*p1) + p2*p2        (separate rn mult + rn adds, no fma)
//   dot  = fma(p2,q2, fma(p1,q1, rn(p0*q0)))   (k-ascending fma chain, zero init)
//   d    = rn(sq_n + sq_m) - 2*dot        (2*dot exact; fused==unfused here)
// Stable insertion (strict <) reproduces jax.lax.top_k tie-breaking (earlier
// index wins on equal distance).
__global__ __launch_bounds__(128) void knn_kernel(const float* __restrict__ p)
{
    __shared__ float ps[NN*3];
    __shared__ float sq[NN];
    int b  = blockIdx.x >> 2;   // 4 blocks / batch
    int nb = blockIdx.x & 3;
    const float* pb = p + (size_t)b * NN * 3;
    for (int i = threadIdx.x; i < NN*3; i += 128) ps[i] = pb[i];
    __syncthreads();
    for (int i = threadIdx.x; i < NN; i += 128) {
        float m0 = __fmul_rn(ps[i*3+0], ps[i*3+0]);
        float m1 = __fmul_rn(ps[i*3+1], ps[i*3+1]);
        float m2 = __fmul_rn(ps[i*3+2], ps[i*3+2]);
        sq[i] = __fadd_rn(__fadd_rn(m0, m1), m2);
    }
    __syncthreads();

    int n = nb * 128 + threadIdx.x;
    float px = ps[n*3+0], py = ps[n*3+1], pz = ps[n*3+2];
    float sn = sq[n];

    float bestd[NS];
    int   besti[NS];
#pragma unroll
    for (int j = 0; j < NS; j++) { bestd[j] = 3.4e38f; besti[j] = 0; }

    for (int m = 0; m < NN; m++) {
        float dot = __fmul_rn(px, ps[m*3+0]);
        dot = fmaf(py, ps[m*3+1], dot);
        dot = fmaf(pz, ps[m*3+2], dot);
        float d = __fsub_rn(__fadd_rn(sn, sq[m]), __fmul_rn(2.0f, dot));
        if (d < bestd[NS-1]) {
            int pos = NS-1;
            while (pos > 0 && bestd[pos-1] > d) {
                bestd[pos] = bestd[pos-1];
                besti[pos] = besti[pos-1];
                pos--;
            }
            bestd[pos] = d;
            besti[pos] = m;
        }
    }
    int row = b*NN + n;
#pragma unroll
    for (int j = 0; j < NS; j++) g_idx[row*NS + j] = besti[j];
}

// ============================ QKV GEMM =======================================
// C[row, c] = sum_k x[b, k, n] * W[k, c] + bias[c]
// row = b*512 + n. Tiles 64x64, BK=32, 256 threads, 4x4 microtile.
__global__ __launch_bounds__(256) void qkv_gemm(
    const float* __restrict__ x,
    const float* __restrict__ Wq, const float* __restrict__ bq,
    const float* __restrict__ Wk, const float* __restrict__ bk,
    const float* __restrict__ Wv, const float* __restrict__ bv)
{
    const float* W; const float* bias; float* out;
    if (blockIdx.z == 0)      { W = Wq; bias = bq; out = g_xq; }
    else if (blockIdx.z == 1) { W = Wk; bias = bk; out = g_xk; }
    else                      { W = Wv; bias = bv; out = g_xv; }

    __shared__ __align__(16) float As[32][68];
    __shared__ __align__(16) float Bs[32][68];

    int tx = threadIdx.x & 15;   // col group
    int ty = threadIdx.x >> 4;   // row group
    int m0 = blockIdx.y * 64;    // global row tile (64 | 512 -> single batch)
    int c0 = blockIdx.x * 64;
    int b  = m0 >> 9;
    int n0 = m0 & 511;
    const float* xb = x + (size_t)b * CC * NN;   // x[b, k, n]

    float acc[4][4];
#pragma unroll
    for (int i = 0; i < 4; i++)
#pragma unroll
        for (int j = 0; j < 4; j++) acc[i][j] = 0.0f;

    for (int k0 = 0; k0 < CC; k0 += 32) {
#pragma unroll
        for (int i = 0; i < 8; i++) {
            int e  = threadIdx.x + i*256;
            int mm = e & 63, kk = e >> 6;
            As[kk][mm] = xb[(size_t)(k0+kk)*NN + n0 + mm];
            Bs[kk][mm] = W[(size_t)(k0+kk)*CC + c0 + mm];
        }
        __syncthreads();
#pragma unroll
        for (int kk = 0; kk < 32; kk++) {
            float4 a4 = *reinterpret_cast<const float4*>(&As[kk][ty*4]);
            float4 b4 = *reinterpret_cast<const float4*>(&Bs[kk][tx*4]);
            float a[4] = {a4.x, a4.y, a4.z, a4.w};
            float bv4[4] = {b4.x, b4.y, b4.z, b4.w};
#pragma unroll
            for (int i = 0; i < 4; i++)
#pragma unroll
                for (int j = 0; j < 4; j++)
                    acc[i][j] = fmaf(a[i], bv4[j], acc[i][j]);
        }
        __syncthreads();
    }

#pragma unroll
    for (int i = 0; i < 4; i++) {
        int row = m0 + ty*4 + i;
#pragma unroll
        for (int j = 0; j < 4; j++) {
            int c = c0 + tx*4 + j;
            out[(size_t)row*CC + c] = acc[i][j] + bias[c];
        }
    }
}

// ============================ main fused kernel ==============================
// One block per (b, n). 256 threads.
__global__ __launch_bounds__(256) void pt_main(
    const float* __restrict__ p,
    const float* __restrict__ p1W,  const float* __restrict__ p1b,
    const float* __restrict__ pbng, const float* __restrict__ pbnb,
    const float* __restrict__ p2W,  const float* __restrict__ p2b,
    const float* __restrict__ bn1g, const float* __restrict__ bn1bv,
    const float* __restrict__ W1,   const float* __restrict__ b1,
    const float* __restrict__ bn2g, const float* __restrict__ bn2bv,
    const float* __restrict__ W2,   const float* __restrict__ b2,
    float* __restrict__ out)
{
    __shared__ __align__(16) float a_s[NS*CC];   // 32 KB: relu(bn1(k - q + pr))
    __shared__ float a2_s[NS*CM];                // 4 KB
    __shared__ float y2_s[NS*CM];                // 4 KB (softmax weights in-place)
    __shared__ float xq_s[CC];                   // 2 KB
    __shared__ float bn1s_s[CC];                 // 2 KB
    __shared__ float bn1o_s[CC];                 // 2 KB
    __shared__ int   idx_s[NS];
    __shared__ float h_s[NS*3];

    const int row = blockIdx.x;          // b*N + n
    const int b   = row >> 9;
    const int tid = threadIdx.x;
    const float RS = rsqrtf(1.0f + 1e-5f);

    // ---- phase A: idx, h (linear_p front), xq row, bn1 coeffs ----
    if (tid < NS) {
        int m = g_idx[row*NS + tid];
        idx_s[tid] = m;
        int gm = b*NN + m;
        float prx = p[gm*3+0] - p[row*3+0];
        float pry = p[gm*3+1] - p[row*3+1];
        float prz = p[gm*3+2] - p[row*3+2];
#pragma unroll
        for (int j = 0; j < 3; j++) {
            float v = prx*p1W[0*3+j] + pry*p1W[1*3+j] + prz*p1W[2*3+j] + p1b[j];
            v = v * (pbng[j] * RS) + pbnb[j];
            h_s[tid*3+j] = fmaxf(v, 0.0f);
        }
    }
    for (int c = tid; c < CC; c += 256) {
        xq_s[c]   = g_xq[(size_t)row*CC + c];
        bn1s_s[c] = bn1g[c] * RS;
        bn1o_s[c] = bn1bv[c];
    }
    __syncthreads();

    // ---- phase B: a = relu(bn1(k_g - xq + pr)) ----
    for (int e = tid; e < NS*CC; e += 256) {
        int j = e >> 9;
        int c = e & 511;
        int m = idx_s[j];
        float pr = h_s[j*3+0]*p2W[c] + h_s[j*3+1]*p2W[CC+c]
                 + h_s[j*3+2]*p2W[2*CC+c] + p2b[c];
        float w = g_xk[(size_t)(b*NN+m)*CC + c] - xq_s[c] + pr;
        w = fmaf(w, bn1s_s[c], bn1o_s[c]);
        a_s[e] = fmaxf(w, 0.0f);
    }
    __syncthreads();

    // ---- GEMM1: (16 x 512) @ (512 x 64); thread = (c, jg of 4 neighbors) ----
    const int c  = tid & 63;
    const int jg = tid >> 6;   // 0..3
    {
        float acc0 = 0.f, acc1 = 0.f, acc2 = 0.f, acc3 = 0.f;
        const float* a0p = &a_s[(jg*4+0)*CC];
        const float* a1p = &a_s[(jg*4+1)*CC];
        const float* a2p = &a_s[(jg*4+2)*CC];
        const float* a3p = &a_s[(jg*4+3)*CC];
        for (int k = 0; k < CC; k += 4) {
            float4 v0 = *reinterpret_cast<const float4*>(a0p + k);
            float4 v1 = *reinterpret_cast<const float4*>(a1p + k);
            float4 v2 = *reinterpret_cast<const float4*>(a2p + k);
            float4 v3 = *reinterpret_cast<const float4*>(a3p + k);
            float w0 = W1[(k+0)*CM + c];
            float w1 = W1[(k+1)*CM + c];
            float w2 = W1[(k+2)*CM + c];
            float w3 = W1[(k+3)*CM + c];
            acc0 = fmaf(v0.x,w0, fmaf(v0.y,w1, fmaf(v0.z,w2, fmaf(v0.w,w3, acc0))));
            acc1 = fmaf(v1.x,w0, fmaf(v1.y,w1, fmaf(v1.z,w2, fmaf(v1.w,w3, acc1))));
            acc2 = fmaf(v2.x,w0, fmaf(v2.y,w1, fmaf(v2.z,w2, fmaf(v2.w,w3, acc2))));
            acc3 = fmaf(v3.x,w0, fmaf(v3.y,w1, fmaf(v3.z,w2, fmaf(v3.w,w3, acc3))));
        }
        float bb   = b1[c];
        float bn2s = bn2g[c] * RS;
        float bn2o = bn2bv[c];
        a2_s[(jg*4+0)*CM + c] = fmaxf(fmaf(acc0 + bb, bn2s, bn2o), 0.0f);
        a2_s[(jg*4+1)*CM + c] = fmaxf(fmaf(acc1 + bb, bn2s, bn2o), 0.0f);
        a2_s[(jg*4+2)*CM + c] = fmaxf(fmaf(acc2 + bb, bn2s, bn2o), 0.0f);
        a2_s[(jg*4+3)*CM + c] = fmaxf(fmaf(acc3 + bb, bn2s, bn2o), 0.0f);
    }
    __syncthreads();

    // ---- GEMM2: (16 x 64) @ (64 x 64) ----
    {
        float acc0 = 0.f, acc1 = 0.f, acc2 = 0.f, acc3 = 0.f;
#pragma unroll 8
        for (int k = 0; k < CM; k++) {
            float wv = W2[k*CM + c];
            acc0 = fmaf(a2_s[(jg*4+0)*CM + k], wv, acc0);
            acc1 = fmaf(a2_s[(jg*4+1)*CM + k], wv, acc1);
            acc2 = fmaf(a2_s[(jg*4+2)*CM + k], wv, acc2);
            acc3 = fmaf(a2_s[(jg*4+3)*CM + k], wv, acc3);
        }
        float bb = b2[c];
        y2_s[(jg*4+0)*CM + c] = acc0 + bb;
        y2_s[(jg*4+1)*CM + c] = acc1 + bb;
        y2_s[(jg*4+2)*CM + c] = acc2 + bb;
        y2_s[(jg*4+3)*CM + c] = acc3 + bb;
    }
    __syncthreads();

    // ---- softmax over the 16 neighbors, per column (threads 0..63) ----
    if (tid < 64) {
        float mx = -3.4e38f;
#pragma unroll
        for (int j = 0; j < NS; j++) mx = fmaxf(mx, y2_s[j*CM + tid]);
        float ex[NS];
        float sum = 0.0f;
#pragma unroll
        for (int j = 0; j < NS; j++) {
            ex[j] = expf(y2_s[j*CM + tid] - mx);
            sum += ex[j];
        }
        float inv = 1.0f / sum;
#pragma unroll
        for (int j = 0; j < NS; j++) y2_s[j*CM + tid] = ex[j] * inv;
    }
    __syncthreads();

    // ---- epilogue: out[cf] = sum_j (xv[m_j][cf] + pr_j[cf]) * w[j][cf%64] ----
    for (int cf = tid; cf < CC; cf += 256) {
        float q0 = p2W[cf], q1 = p2W[CC+cf], q2 = p2W[2*CC+cf], qb = p2b[cf];
        int cc = cf & 63;
        float acc = 0.0f;
#pragma unroll
        for (int j = 0; j < NS; j++) {
            int m = idx_s[j];
            float pr = h_s[j*3+0]*q0 + h_s[j*3+1]*q1 + h_s[j*3+2]*q2 + qb;
            float v  = g_xv[(size_t)(b*NN+m)*CC + cf] + pr;
            acc = fmaf(v, y2_s[j*CM + cc], acc);
        }
        out[(size_t)row*CC + cf] = acc;
    }
}

// ============================ launcher =======================================
extern "C" void kernel_launch(void* const* d_in, const int* in_sizes, int n_in,
                              void* d_out, int out_size)
{
    const float* p    = (const float*)d_in[0];
    const float* x    = (const float*)d_in[1];
    const float* Wq   = (const float*)d_in[2];
    const float* bq   = (const float*)d_in[3];
    const float* Wk   = (const float*)d_in[4];
    const float* bk   = (const float*)d_in[5];
    const float* Wv   = (const float*)d_in[6];
    const float* bv   = (const float*)d_in[7];
    const float* p1W  = (const float*)d_in[8];
    const float* p1b  = (const float*)d_in[9];
    const float* pbng = (const float*)d_in[10];
    const float* pbnb = (const float*)d_in[11];
    const float* p2W  = (const float*)d_in[12];
    const float* p2b  = (const float*)d_in[13];
    const float* bn1g = (const float*)d_in[14];
    const float* bn1b = (const float*)d_in[15];
    const float* W1   = (const float*)d_in[16];
    const float* b1   = (const float*)d_in[17];
    const float* bn2g = (const float*)d_in[18];
    const float* bn2b = (const float*)d_in[19];
    const float* W2   = (const float*)d_in[20];
    const float* b2   = (const float*)d_in[21];
    float* out = (float*)d_out;

    knn_kernel<<<BB*4, 128>>>(p);
    qkv_gemm<<<dim3(CC/64, ROWS/64, 3), 256>>>(x, Wq, bq, Wk, bk, Wv, bv);
    pt_main<<<ROWS, 256>>>(p, p1W, p1b, pbng, pbnb, p2W, p2b,
                           bn1g, bn1b, W1, b1, bn2g, bn2b, W2, b2, out);
}

// round 4
// speedup vs baseline: 1.5804x; 1.5804x over previous
#include <cuda_runtime.h>
#include <math.h>

#define BB 16
#define NN 512
#define CC 512
#define NS 16
#define CM 64           // CC / S
#define ROWS (BB*NN)    // 8192
#define ASTRIDE 516     // padded a_s row stride (floats): 16B-aligned, kills jg bank conflicts

// ---------------- scratch (static device globals; no allocation) -------------
__device__ float g_xq[ROWS*CC];
__device__ float g_xk[ROWS*CC];
__device__ float g_xv[ROWS*CC];
__device__ int   g_idx[ROWS*NS];

// ============================ kNN kernel =====================================
// Warp per query. Each lane owns 16 candidate points (m = lane*16+i) kept in
// registers; 16 rounds of (local unrolled argmin -> warp 64-bit key min).
// Key = (ordered(d)<<32)|m so ties pick the smaller index m, matching
// jax.lax.top_k. Distance arithmetic is ulp-identical to the reference:
//   sq  = (p0*p0 + p1*p1) + p2*p2      (rn mult + rn adds, no fma)
//   dot = fma(p2,q2, fma(p1,q1, rn(p0*q0)))
//   d   = rn(sq_n + sq_m) - 2*dot
__global__ __launch_bounds__(256) void knn_kernel(const float* __restrict__ p)
{
    __shared__ float ps[NN*3];
    __shared__ float sq[NN];
    const int b    = blockIdx.x >> 6;       // 64 blocks per batch
    const int warp = threadIdx.x >> 5;      // 8 warps -> 8 queries per block
    const int lane = threadIdx.x & 31;
    const float* pb = p + (size_t)b * NN * 3;
    for (int i = threadIdx.x; i < NN*3; i += 256) ps[i] = pb[i];
    __syncthreads();
    for (int i = threadIdx.x; i < NN; i += 256) {
        float m0 = __fmul_rn(ps[i*3+0], ps[i*3+0]);
        float m1 = __fmul_rn(ps[i*3+1], ps[i*3+1]);
        float m2 = __fmul_rn(ps[i*3+2], ps[i*3+2]);
        sq[i] = __fadd_rn(__fadd_rn(m0, m1), m2);
    }
    __syncthreads();

    const int n = (blockIdx.x & 63) * 8 + warp;
    const float px = ps[n*3+0], py = ps[n*3+1], pz = ps[n*3+2];
    const float sn = sq[n];

    float d[16];
#pragma unroll
    for (int i = 0; i < 16; i++) {
        int m = lane * 16 + i;
        float dot = __fmul_rn(px, ps[m*3+0]);
        dot = fmaf(py, ps[m*3+1], dot);
        dot = fmaf(pz, ps[m*3+2], dot);
        d[i] = __fsub_rn(__fadd_rn(sn, sq[m]), __fmul_rn(2.0f, dot));
    }

    const int row = b*NN + n;
    const float INF = __int_as_float(0x7f800000);
#pragma unroll 1
    for (int t = 0; t < NS; t++) {
        // local argmin (strict < keeps lowest i -> lowest m among lane's ties)
        float bd = d[0]; int bi = 0;
#pragma unroll
        for (int i = 1; i < 16; i++) if (d[i] < bd) { bd = d[i]; bi = i; }
        // monotonic unsigned encoding of float
        int ib = __float_as_int(bd);
        unsigned u = (unsigned)ib ^ ((ib < 0) ? 0xFFFFFFFFu : 0x80000000u);
        unsigned long long key = ((unsigned long long)u << 32) | (unsigned)(lane*16 + bi);
#pragma unroll
        for (int s = 16; s > 0; s >>= 1) {
            unsigned long long o = __shfl_xor_sync(0xFFFFFFFFu, key, s);
            if (o < key) key = o;
        }
        int win_m = (int)(key & 0xFFFFFFFFu);
        if ((win_m >> 4) == lane) {
            int wi = win_m & 15;
#pragma unroll
            for (int i = 0; i < 16; i++) if (i == wi) d[i] = INF;
        }
        if (lane == 0) g_idx[row*NS + t] = win_m;
    }
}

// ============================ QKV GEMM =======================================
// 128x128 block tile, BK=16, 256 threads, 8x8 microtile split 4+4 each dim
// (conflict-free LDS.128). FMA-bound (~1B/FMA from shared).
__global__ __launch_bounds__(256) void qkv_gemm(
    const float* __restrict__ x,
    const float* __restrict__ Wq, const float* __restrict__ bq,
    const float* __restrict__ Wk, const float* __restrict__ bk,
    const float* __restrict__ Wv, const float* __restrict__ bv)
{
    const float* W; const float* bias; float* out;
    if (blockIdx.z == 0)      { W = Wq; bias = bq; out = g_xq; }
    else if (blockIdx.z == 1) { W = Wk; bias = bk; out = g_xk; }
    else                      { W = Wv; bias = bv; out = g_xv; }

    __shared__ __align__(16) float As[16][132];
    __shared__ __align__(16) float Bs[16][132];

    const int tid = threadIdx.x;
    const int tx = tid & 15;       // col group: cols tx*4..+3 and 64+tx*4..+3
    const int ty = tid >> 4;       // row group: rows ty*4..+3 and 64+ty*4..+3
    const int m0 = blockIdx.y * 128;   // 128 | 512 so one batch per tile
    const int c0 = blockIdx.x * 128;
    const int b  = m0 >> 9;
    const int n0 = m0 & 511;
    const float* xb = x + (size_t)b * CC * NN;   // x[b, k, n]

    float acc[8][8];
#pragma unroll
    for (int i = 0; i < 8; i++)
#pragma unroll
        for (int j = 0; j < 8; j++) acc[i][j] = 0.0f;

    for (int k0 = 0; k0 < CC; k0 += 16) {
        // load 16x128 A and B tiles: 512 float4 each, 2 per thread
#pragma unroll
        for (int i = 0; i < 2; i++) {
            int f  = tid + i*256;
            int kk = f >> 5;
            int mm = (f & 31) * 4;
            *reinterpret_cast<float4*>(&As[kk][mm]) =
                *reinterpret_cast<const float4*>(&xb[(size_t)(k0+kk)*NN + n0 + mm]);
            *reinterpret_cast<float4*>(&Bs[kk][mm]) =
                *reinterpret_cast<const float4*>(&W[(size_t)(k0+kk)*CC + c0 + mm]);
        }
        __syncthreads();
#pragma unroll
        for (int kk = 0; kk < 16; kk++) {
            float4 a0 = *reinterpret_cast<const float4*>(&As[kk][ty*4]);
            float4 a1 = *reinterpret_cast<const float4*>(&As[kk][64 + ty*4]);
            float4 b0 = *reinterpret_cast<const float4*>(&Bs[kk][tx*4]);
            float4 b1 = *reinterpret_cast<const float4*>(&Bs[kk][64 + tx*4]);
            float av[8] = {a0.x,a0.y,a0.z,a0.w, a1.x,a1.y,a1.z,a1.w};
            float bvv[8] = {b0.x,b0.y,b0.z,b0.w, b1.x,b1.y,b1.z,b1.w};
#pragma unroll
            for (int i = 0; i < 8; i++)
#pragma unroll
                for (int j = 0; j < 8; j++)
                    acc[i][j] = fmaf(av[i], bvv[j], acc[i][j]);
        }
        __syncthreads();
    }

#pragma unroll
    for (int i = 0; i < 8; i++) {
        int row = m0 + ((i < 4) ? (ty*4 + i) : (64 + ty*4 + i - 4));
#pragma unroll
        for (int jh = 0; jh < 2; jh++) {
            int c = c0 + ((jh == 0) ? (tx*4) : (64 + tx*4));
            float4 v;
            v.x = acc[i][jh*4+0] + bias[c+0];
            v.y = acc[i][jh*4+1] + bias[c+1];
            v.z = acc[i][jh*4+2] + bias[c+2];
            v.w = acc[i][jh*4+3] + bias[c+3];
            *reinterpret_cast<float4*>(&out[(size_t)row*CC + c]) = v;
        }
    }
}

// ============================ main fused kernel ==============================
// One block per (b, n). 256 threads.
__global__ __launch_bounds__(256) void pt_main(
    const float* __restrict__ p,
    const float* __restrict__ p1W,  const float* __restrict__ p1b,
    const float* __restrict__ pbng, const float* __restrict__ pbnb,
    const float* __restrict__ p2W,  const float* __restrict__ p2b,
    const float* __restrict__ bn1g, const float* __restrict__ bn1bv,
    const float* __restrict__ W1,   const float* __restrict__ b1,
    const float* __restrict__ bn2g, const float* __restrict__ bn2bv,
    const float* __restrict__ W2,   const float* __restrict__ b2,
    float* __restrict__ out)
{
    __shared__ __align__(16) float a_s[NS*ASTRIDE];  // 33 KB (also reused for GEMM1 partials)
    __shared__ float a2_s[NS*CM];                    // 4 KB
    __shared__ float y2_s[NS*CM];                    // 4 KB (softmax weights)
    __shared__ float xq_s[CC];                       // 2 KB
    __shared__ float bn1s_s[CC];                     // 2 KB
    __shared__ float bn1o_s[CC];                     // 2 KB
    __shared__ int   idx_s[NS];
    __shared__ float h_s[NS*3];

    const int row = blockIdx.x;          // b*N + n
    const int b   = row >> 9;
    const int tid = threadIdx.x;
    const float RS = rsqrtf(1.0f + 1e-5f);

    // ---- phase A: idx, h (linear_p front), xq row, bn1 coeffs ----
    if (tid < NS) {
        int m = g_idx[row*NS + tid];
        idx_s[tid] = m;
        int gm = b*NN + m;
        float prx = p[gm*3+0] - p[row*3+0];
        float pry = p[gm*3+1] - p[row*3+1];
        float prz = p[gm*3+2] - p[row*3+2];
#pragma unroll
        for (int j = 0; j < 3; j++) {
            float v = prx*p1W[0*3+j] + pry*p1W[1*3+j] + prz*p1W[2*3+j] + p1b[j];
            v = v * (pbng[j] * RS) + pbnb[j];
            h_s[tid*3+j] = fmaxf(v, 0.0f);
        }
    }
    for (int c = tid; c < CC; c += 256) {
        xq_s[c]   = g_xq[(size_t)row*CC + c];
        bn1s_s[c] = bn1g[c] * RS;
        bn1o_s[c] = bn1bv[c];
    }
    __syncthreads();

    // ---- phase B: a = relu(bn1(k_g - xq + pr)) ----
    for (int e = tid; e < NS*CC; e += 256) {
        int j = e >> 9;
        int c = e & 511;
        int m = idx_s[j];
        float pr = h_s[j*3+0]*p2W[c] + h_s[j*3+1]*p2W[CC+c]
                 + h_s[j*3+2]*p2W[2*CC+c] + p2b[c];
        float w = g_xk[(size_t)(b*NN+m)*CC + c] - xq_s[c] + pr;
        w = fmaf(w, bn1s_s[c], bn1o_s[c]);
        a_s[j*ASTRIDE + c] = fmaxf(w, 0.0f);
    }
    __syncthreads();

    // ---- GEMM1: (16 x 512) @ (512 x 64), 4j x 4c x k-split-4 register tile --
    const int cg = tid & 15;          // c4 = cg*4
    const int jg = (tid >> 4) & 3;    // j = jg*4 .. +3
    const int ks = tid >> 6;          // k slice: ks*128 .. +127
    {
        float acc[4][4];
#pragma unroll
        for (int i = 0; i < 4; i++)
#pragma unroll
            for (int j = 0; j < 4; j++) acc[i][j] = 0.0f;

        const int c4 = cg * 4;
        const float* W1p = W1 + (size_t)ks*128*CM + c4;
        const float* ap  = &a_s[jg*4*ASTRIDE + ks*128];
#pragma unroll 4
        for (int k = 0; k < 128; k += 4) {
            float4 av[4];
#pragma unroll
            for (int j = 0; j < 4; j++)
                av[j] = *reinterpret_cast<const float4*>(ap + j*ASTRIDE + k);
#pragma unroll
            for (int kk = 0; kk < 4; kk++) {
                float4 wv = *reinterpret_cast<const float4*>(W1p + (k+kk)*CM);
                float wa[4] = {wv.x, wv.y, wv.z, wv.w};
                float aa[4] = { (kk==0?av[0].x:kk==1?av[0].y:kk==2?av[0].z:av[0].w),
                                (kk==0?av[1].x:kk==1?av[1].y:kk==2?av[1].z:av[1].w),
                                (kk==0?av[2].x:kk==1?av[2].y:kk==2?av[2].z:av[2].w),
                                (kk==0?av[3].x:kk==1?av[3].y:kk==2?av[3].z:av[3].w) };
#pragma unroll
                for (int j = 0; j < 4; j++)
#pragma unroll
                    for (int cc = 0; cc < 4; cc++)
                        acc[j][cc] = fmaf(aa[j], wa[cc], acc[j][cc]);
            }
        }
        __syncthreads();   // everyone done reading a_s
        // store partials into a_s front region: [ks][jj][c] flat 4096 floats
#pragma unroll
        for (int j = 0; j < 4; j++) {
            float4 v = make_float4(acc[j][0], acc[j][1], acc[j][2], acc[j][3]);
            *reinterpret_cast<float4*>(&a_s[ks*1024 + (jg*4+j)*CM + c4]) = v;
        }
    }
    __syncthreads();

    // ---- reduce k-slices + bias + bn2 + relu -> a2_s ----
#pragma unroll
    for (int i = 0; i < 4; i++) {
        int o = tid + i*256;          // o = jj*64 + c
        int c = o & 63;
        float s = a_s[o] + a_s[1024 + o] + a_s[2048 + o] + a_s[3072 + o];
        s += b1[c];
        s = fmaf(s, bn2g[c]*RS, bn2bv[c]);
        a2_s[o] = fmaxf(s, 0.0f);
    }
    __syncthreads();

    // ---- GEMM2: (16 x 64) @ (64 x 64) ----
    const int c  = tid & 63;
    const int jq = tid >> 6;   // 0..3, handles j = jq*4..+3
    {
        float acc0 = 0.f, acc1 = 0.f, acc2 = 0.f, acc3 = 0.f;
#pragma unroll 8
        for (int k = 0; k < CM; k++) {
            float wv = W2[k*CM + c];
            acc0 = fmaf(a2_s[(jq*4+0)*CM + k], wv, acc0);
            acc1 = fmaf(a2_s[(jq*4+1)*CM + k], wv, acc1);
            acc2 = fmaf(a2_s[(jq*4+2)*CM + k], wv, acc2);
            acc3 = fmaf(a2_s[(jq*4+3)*CM + k], wv, acc3);
        }
        float bb = b2[c];
        y2_s[(jq*4+0)*CM + c] = acc0 + bb;
        y2_s[(jq*4+1)*CM + c] = acc1 + bb;
        y2_s[(jq*4+2)*CM + c] = acc2 + bb;
        y2_s[(jq*4+3)*CM + c] = acc3 + bb;
    }
    __syncthreads();

    // ---- softmax over the 16 neighbors, per column (threads 0..63) ----
    if (tid < 64) {
        float mx = -3.4e38f;
#pragma unroll
        for (int j = 0; j < NS; j++) mx = fmaxf(mx, y2_s[j*CM + tid]);
        float ex[NS];
        float sum = 0.0f;
#pragma unroll
        for (int j = 0; j < NS; j++) {
            ex[j] = expf(y2_s[j*CM + tid] - mx);
            sum += ex[j];
        }
        float inv = 1.0f / sum;
#pragma unroll
        for (int j = 0; j < NS; j++) y2_s[j*CM + tid] = ex[j] * inv;
    }
    __syncthreads();

    // ---- epilogue: out[cf] = sum_j (xv[m_j][cf] + pr_j[cf]) * w[j][cf%64] ----
    for (int cf = tid; cf < CC; cf += 256) {
        float q0 = p2W[cf], q1 = p2W[CC+cf], q2 = p2W[2*CC+cf], qb = p2b[cf];
        int cc = cf & 63;
        float acc = 0.0f;
#pragma unroll
        for (int j = 0; j < NS; j++) {
            int m = idx_s[j];
            float pr = h_s[j*3+0]*q0 + h_s[j*3+1]*q1 + h_s[j*3+2]*q2 + qb;
            float v  = g_xv[(size_t)(b*NN+m)*CC + cf] + pr;
            acc = fmaf(v, y2_s[j*CM + cc], acc);
        }
        out[(size_t)row*CC + cf] = acc;
    }
}

// ============================ launcher =======================================
extern "C" void kernel_launch(void* const* d_in, const int* in_sizes, int n_in,
                              void* d_out, int out_size)
{
    const float* p    = (const float*)d_in[0];
    const float* x    = (const float*)d_in[1];
    const float* Wq   = (const float*)d_in[2];
    const float* bq   = (const float*)d_in[3];
    const float* Wk   = (const float*)d_in[4];
    const float* bk   = (const float*)d_in[5];
    const float* Wv   = (const float*)d_in[6];
    const float* bv   = (const float*)d_in[7];
    const float* p1W  = (const float*)d_in[8];
    const float* p1b  = (const float*)d_in[9];
    const float* pbng = (const float*)d_in[10];
    const float* pbnb = (const float*)d_in[11];
    const float* p2W  = (const float*)d_in[12];
    const float* p2b  = (const float*)d_in[13];
    const float* bn1g = (const float*)d_in[14];
    const float* bn1b = (const float*)d_in[15];
    const float* W1   = (const float*)d_in[16];
    const float* b1   = (const float*)d_in[17];
    const float* bn2g = (const float*)d_in[18];
    const float* bn2b = (const float*)d_in[19];
    const float* W2   = (const float*)d_in[20];
    const float* b2   = (const float*)d_in[21];
    float* out = (float*)d_out;

    knn_kernel<<<BB*64, 256>>>(p);
    qkv_gemm<<<dim3(CC/128, ROWS/128, 3), 256>>>(x, Wq, bq, Wk, bk, Wv, bv);
    pt_main<<<ROWS, 256>>>(p, p1W, p1b, pbng, pbnb, p2W, p2b,
                           bn1g, bn1b, W1, b1, bn2g, bn2b, W2, b2, out);
}

// round 5
// speedup vs baseline: 1.6807x; 1.0635x over previous
#include <cuda_runtime.h>
#include <math.h>

#define BB 16
#define NN 512
#define CC 512
#define NS 16
#define CM 64           // CC / S
#define ROWS (BB*NN)    // 8192
#define ASTRIDE 516     // padded a_s row stride (floats)

typedef unsigned long long ull;

// packed f32x2 helpers (FFMA2 path — only reachable via explicit PTX)
__device__ __forceinline__ void ffma2(ull &d, ull a, ull b) {
    asm("fma.rn.f32x2 %0, %1, %2, %0;" : "+l"(d) : "l"(a), "l"(b));
}
__device__ __forceinline__ ull pack2(float lo, float hi) {
    ull r; asm("mov.b64 %0, {%1, %2};" : "=l"(r) : "f"(lo), "f"(hi)); return r;
}
__device__ __forceinline__ void unpack2(float &lo, float &hi, ull v) {
    asm("mov.b64 {%0, %1}, %2;" : "=f"(lo), "=f"(hi) : "l"(v));
}

// ---------------- scratch (static device globals; no allocation) -------------
__device__ float g_xq[ROWS*CC];
__device__ float g_xk[ROWS*CC];
__device__ float g_xv[ROWS*CC];
__device__ int   g_idx[ROWS*NS];

// ============================ kNN kernel =====================================
// Warp per query; ulp-identical distance arithmetic to the reference;
// 64-bit key warp-min reproduces jax.lax.top_k tie-breaking.
__global__ __launch_bounds__(256) void knn_kernel(const float* __restrict__ p)
{
    __shared__ float ps[NN*3];
    __shared__ float sq[NN];
    const int b    = blockIdx.x >> 6;
    const int warp = threadIdx.x >> 5;
    const int lane = threadIdx.x & 31;
    const float* pb = p + (size_t)b * NN * 3;
    for (int i = threadIdx.x; i < NN*3; i += 256) ps[i] = pb[i];
    __syncthreads();
    for (int i = threadIdx.x; i < NN; i += 256) {
        float m0 = __fmul_rn(ps[i*3+0], ps[i*3+0]);
        float m1 = __fmul_rn(ps[i*3+1], ps[i*3+1]);
        float m2 = __fmul_rn(ps[i*3+2], ps[i*3+2]);
        sq[i] = __fadd_rn(__fadd_rn(m0, m1), m2);
    }
    __syncthreads();

    const int n = (blockIdx.x & 63) * 8 + warp;
    const float px = ps[n*3+0], py = ps[n*3+1], pz = ps[n*3+2];
    const float sn = sq[n];

    float d[16];
#pragma unroll
    for (int i = 0; i < 16; i++) {
        int m = lane * 16 + i;
        float dot = __fmul_rn(px, ps[m*3+0]);
        dot = fmaf(py, ps[m*3+1], dot);
        dot = fmaf(pz, ps[m*3+2], dot);
        d[i] = __fsub_rn(__fadd_rn(sn, sq[m]), __fmul_rn(2.0f, dot));
    }

    const int row = b*NN + n;
    const float INF = __int_as_float(0x7f800000);
#pragma unroll 1
    for (int t = 0; t < NS; t++) {
        float bd = d[0]; int bi = 0;
#pragma unroll
        for (int i = 1; i < 16; i++) if (d[i] < bd) { bd = d[i]; bi = i; }
        int ib = __float_as_int(bd);
        unsigned u = (unsigned)ib ^ ((ib < 0) ? 0xFFFFFFFFu : 0x80000000u);
        ull key = ((ull)u << 32) | (unsigned)(lane*16 + bi);
#pragma unroll
        for (int s = 16; s > 0; s >>= 1) {
            ull o = __shfl_xor_sync(0xFFFFFFFFu, key, s);
            if (o < key) key = o;
        }
        int win_m = (int)(key & 0xFFFFFFFFu);
        if ((win_m >> 4) == lane) {
            int wi = win_m & 15;
#pragma unroll
            for (int i = 0; i < 16; i++) if (i == wi) d[i] = INF;
        }
        if (lane == 0) g_idx[row*NS + t] = win_m;
    }
}

// ============================ QKV GEMM =======================================
// 128x128 block tile, BK=16, 256 threads, 8x8 microtile; accumulators packed
// f32x2 along n (FFMA2). Rounding identical to scalar fmaf.
__global__ __launch_bounds__(256) void qkv_gemm(
    const float* __restrict__ x,
    const float* __restrict__ Wq, const float* __restrict__ bq,
    const float* __restrict__ Wk, const float* __restrict__ bk,
    const float* __restrict__ Wv, const float* __restrict__ bv)
{
    const float* W; const float* bias; float* out;
    if (blockIdx.z == 0)      { W = Wq; bias = bq; out = g_xq; }
    else if (blockIdx.z == 1) { W = Wk; bias = bk; out = g_xk; }
    else                      { W = Wv; bias = bv; out = g_xv; }

    __shared__ __align__(16) float As[16][132];
    __shared__ __align__(16) float Bs[16][132];

    const int tid = threadIdx.x;
    const int tx = tid & 15;
    const int ty = tid >> 4;
    const int m0 = blockIdx.y * 128;
    const int c0 = blockIdx.x * 128;
    const int b  = m0 >> 9;
    const int n0 = m0 & 511;
    const float* xb = x + (size_t)b * CC * NN;

    ull acc[8][4];
#pragma unroll
    for (int i = 0; i < 8; i++)
#pragma unroll
        for (int j = 0; j < 4; j++) acc[i][j] = 0ULL;

    for (int k0 = 0; k0 < CC; k0 += 16) {
#pragma unroll
        for (int i = 0; i < 2; i++) {
            int f  = tid + i*256;
            int kk = f >> 5;
            int mm = (f & 31) * 4;
            *reinterpret_cast<float4*>(&As[kk][mm]) =
                *reinterpret_cast<const float4*>(&xb[(size_t)(k0+kk)*NN + n0 + mm]);
            *reinterpret_cast<float4*>(&Bs[kk][mm]) =
                *reinterpret_cast<const float4*>(&W[(size_t)(k0+kk)*CC + c0 + mm]);
        }
        __syncthreads();
#pragma unroll
        for (int kk = 0; kk < 16; kk++) {
            float4 a0 = *reinterpret_cast<const float4*>(&As[kk][ty*4]);
            float4 a1 = *reinterpret_cast<const float4*>(&As[kk][64 + ty*4]);
            float4 b0 = *reinterpret_cast<const float4*>(&Bs[kk][tx*4]);
            float4 b1 = *reinterpret_cast<const float4*>(&Bs[kk][64 + tx*4]);
            ull bp0 = pack2(b0.x, b0.y);
            ull bp1 = pack2(b0.z, b0.w);
            ull bp2 = pack2(b1.x, b1.y);
            ull bp3 = pack2(b1.z, b1.w);
            float av[8] = {a0.x,a0.y,a0.z,a0.w, a1.x,a1.y,a1.z,a1.w};
#pragma unroll
            for (int i = 0; i < 8; i++) {
                ull ad = pack2(av[i], av[i]);
                ffma2(acc[i][0], ad, bp0);
                ffma2(acc[i][1], ad, bp1);
                ffma2(acc[i][2], ad, bp2);
                ffma2(acc[i][3], ad, bp3);
            }
        }
        __syncthreads();
    }

#pragma unroll
    for (int i = 0; i < 8; i++) {
        int row = m0 + ((i < 4) ? (ty*4 + i) : (64 + ty*4 + i - 4));
#pragma unroll
        for (int jh = 0; jh < 2; jh++) {
            int c = c0 + ((jh == 0) ? (tx*4) : (64 + tx*4));
            float e0,e1,e2,e3;
            unpack2(e0, e1, acc[i][jh*2+0]);
            unpack2(e2, e3, acc[i][jh*2+1]);
            float4 v;
            v.x = e0 + bias[c+0];
            v.y = e1 + bias[c+1];
            v.z = e2 + bias[c+2];
            v.w = e3 + bias[c+3];
            *reinterpret_cast<float4*>(&out[(size_t)row*CC + c]) = v;
        }
    }
}

// ============================ main fused kernel ==============================
__global__ __launch_bounds__(256) void pt_main(
    const float* __restrict__ p,
    const float* __restrict__ p1W,  const float* __restrict__ p1b,
    const float* __restrict__ pbng, const float* __restrict__ pbnb,
    const float* __restrict__ p2W,  const float* __restrict__ p2b,
    const float* __restrict__ bn1g, const float* __restrict__ bn1bv,
    const float* __restrict__ W1,   const float* __restrict__ b1,
    const float* __restrict__ bn2g, const float* __restrict__ bn2bv,
    const float* __restrict__ W2,   const float* __restrict__ b2,
    float* __restrict__ out)
{
    __shared__ __align__(16) float a_s[NS*ASTRIDE];  // 33 KB (reused for partials)
    __shared__ __align__(16) float a2_s[NS*CM];      // 4 KB
    __shared__ float y2_s[NS*CM];                    // 4 KB
    __shared__ float xq_s[CC];
    __shared__ float bn1s_s[CC];
    __shared__ float bn1o_s[CC];
    __shared__ int   idx_s[NS];
    __shared__ float h_s[NS*3];

    const int row = blockIdx.x;
    const int b   = row >> 9;
    const int tid = threadIdx.x;
    const float RS = rsqrtf(1.0f + 1e-5f);

    // ---- phase A ----
    if (tid < NS) {
        int m = g_idx[row*NS + tid];
        idx_s[tid] = m;
        int gm = b*NN + m;
        float prx = p[gm*3+0] - p[row*3+0];
        float pry = p[gm*3+1] - p[row*3+1];
        float prz = p[gm*3+2] - p[row*3+2];
#pragma unroll
        for (int j = 0; j < 3; j++) {
            float v = prx*p1W[0*3+j] + pry*p1W[1*3+j] + prz*p1W[2*3+j] + p1b[j];
            v = v * (pbng[j] * RS) + pbnb[j];
            h_s[tid*3+j] = fmaxf(v, 0.0f);
        }
    }
    for (int c = tid; c < CC; c += 256) {
        xq_s[c]   = g_xq[(size_t)row*CC + c];
        bn1s_s[c] = bn1g[c] * RS;
        bn1o_s[c] = bn1bv[c];
    }
    __syncthreads();

    // ---- phase B: a = relu(bn1(k_g - xq + pr)) ----
    for (int e = tid; e < NS*CC; e += 256) {
        int j = e >> 9;
        int c = e & 511;
        int m = idx_s[j];
        float pr = h_s[j*3+0]*p2W[c] + h_s[j*3+1]*p2W[CC+c]
                 + h_s[j*3+2]*p2W[2*CC+c] + p2b[c];
        float w = g_xk[(size_t)(b*NN+m)*CC + c] - xq_s[c] + pr;
        w = fmaf(w, bn1s_s[c], bn1o_s[c]);
        a_s[j*ASTRIDE + c] = fmaxf(w, 0.0f);
    }
    __syncthreads();

    // ---- GEMM1: (16x512)@(512x64), 4j x (2x f32x2 c-pairs) x k-split-4 ----
    const int cg = tid & 15;          // c4 = cg*4
    const int jg = (tid >> 4) & 3;    // j = jg*4 .. +3
    const int ks = tid >> 6;          // k slice ks*128..+127
    {
        ull acc[4][2];
#pragma unroll
        for (int i = 0; i < 4; i++) { acc[i][0] = 0ULL; acc[i][1] = 0ULL; }

        const int c4 = cg * 4;
        const float* W1p = W1 + (size_t)ks*128*CM + c4;
        const float* ap  = &a_s[jg*4*ASTRIDE + ks*128];
#pragma unroll 4
        for (int k = 0; k < 128; k += 4) {
            float4 av[4];
#pragma unroll
            for (int j = 0; j < 4; j++)
                av[j] = *reinterpret_cast<const float4*>(ap + j*ASTRIDE + k);
#pragma unroll
            for (int kk = 0; kk < 4; kk++) {
                float4 wv = *reinterpret_cast<const float4*>(W1p + (k+kk)*CM);
                ull wp0 = pack2(wv.x, wv.y);
                ull wp1 = pack2(wv.z, wv.w);
#pragma unroll
                for (int j = 0; j < 4; j++) {
                    float a = (kk==0?av[j].x:kk==1?av[j].y:kk==2?av[j].z:av[j].w);
                    ull ad = pack2(a, a);
                    ffma2(acc[j][0], ad, wp0);
                    ffma2(acc[j][1], ad, wp1);
                }
            }
        }
        __syncthreads();   // done reading a_s
#pragma unroll
        for (int j = 0; j < 4; j++) {
            float e0,e1,e2,e3;
            unpack2(e0, e1, acc[j][0]);
            unpack2(e2, e3, acc[j][1]);
            *reinterpret_cast<float4*>(&a_s[ks*1024 + (jg*4+j)*CM + c4]) =
                make_float4(e0, e1, e2, e3);
        }
    }
    __syncthreads();

    // ---- reduce k-slices + bias + bn2 + relu -> a2_s ----
#pragma unroll
    for (int i = 0; i < 4; i++) {
        int o = tid + i*256;
        int c = o & 63;
        float s = a_s[o] + a_s[1024 + o] + a_s[2048 + o] + a_s[3072 + o];
        s += b1[c];
        s = fmaf(s, bn2g[c]*RS, bn2bv[c]);
        a2_s[o] = fmaxf(s, 0.0f);
    }
    __syncthreads();

    // ---- GEMM2: (16x64)@(64x64), packed along k (even/odd partial sums) ----
    const int c  = tid & 63;
    const int jq = tid >> 6;
    {
        ull s0 = 0ULL, s1 = 0ULL, s2 = 0ULL, s3 = 0ULL;
#pragma unroll 8
        for (int k = 0; k < CM; k += 2) {
            ull wp = pack2(W2[k*CM + c], W2[(k+1)*CM + c]);
            ull a0 = *reinterpret_cast<const ull*>(&a2_s[(jq*4+0)*CM + k]);
            ull a1 = *reinterpret_cast<const ull*>(&a2_s[(jq*4+1)*CM + k]);
            ull a2v = *reinterpret_cast<const ull*>(&a2_s[(jq*4+2)*CM + k]);
            ull a3 = *reinterpret_cast<const ull*>(&a2_s[(jq*4+3)*CM + k]);
            ffma2(s0, a0, wp);
            ffma2(s1, a1, wp);
            ffma2(s2, a2v, wp);
            ffma2(s3, a3, wp);
        }
        float bb = b2[c];
        float lo, hi;
        unpack2(lo, hi, s0); y2_s[(jq*4+0)*CM + c] = lo + hi + bb;
        unpack2(lo, hi, s1); y2_s[(jq*4+1)*CM + c] = lo + hi + bb;
        unpack2(lo, hi, s2); y2_s[(jq*4+2)*CM + c] = lo + hi + bb;
        unpack2(lo, hi, s3); y2_s[(jq*4+3)*CM + c] = lo + hi + bb;
    }
    __syncthreads();

    // ---- softmax over 16 neighbors, per column ----
    if (tid < 64) {
        float mx = -3.4e38f;
#pragma unroll
        for (int j = 0; j < NS; j++) mx = fmaxf(mx, y2_s[j*CM + tid]);
        float ex[NS];
        float sum = 0.0f;
#pragma unroll
        for (int j = 0; j < NS; j++) {
            ex[j] = expf(y2_s[j*CM + tid] - mx);
            sum += ex[j];
        }
        float inv = 1.0f / sum;
#pragma unroll
        for (int j = 0; j < NS; j++) y2_s[j*CM + tid] = ex[j] * inv;
    }
    __syncthreads();

    // ---- epilogue ----
    for (int cf = tid; cf < CC; cf += 256) {
        float q0 = p2W[cf], q1 = p2W[CC+cf], q2 = p2W[2*CC+cf], qb = p2b[cf];
        int cc = cf & 63;
        float acc = 0.0f;
#pragma unroll
        for (int j = 0; j < NS; j++) {
            int m = idx_s[j];
            float pr = h_s[j*3+0]*q0 + h_s[j*3+1]*q1 + h_s[j*3+2]*q2 + qb;
            float v  = g_xv[(size_t)(b*NN+m)*CC + cf] + pr;
            acc = fmaf(v, y2_s[j*CM + cc], acc);
        }
        out[(size_t)row*CC + cf] = acc;
    }
}

// ============================ launcher =======================================
extern "C" void kernel_launch(void* const* d_in, const int* in_sizes, int n_in,
                              void* d_out, int out_size)
{
    const float* p    = (const float*)d_in[0];
    const float* x    = (const float*)d_in[1];
    const float* Wq   = (const float*)d_in[2];
    const float* bq   = (const float*)d_in[3];
    const float* Wk   = (const float*)d_in[4];
    const float* bk   = (const float*)d_in[5];
    const float* Wv   = (const float*)d_in[6];
    const float* bv   = (const float*)d_in[7];
    const float* p1W  = (const float*)d_in[8];
    const float* p1b  = (const float*)d_in[9];
    const float* pbng = (const float*)d_in[10];
    const float* pbnb = (const float*)d_in[11];
    const float* p2W  = (const float*)d_in[12];
    const float* p2b  = (const float*)d_in[13];
    const float* bn1g = (const float*)d_in[14];
    const float* bn1b = (const float*)d_in[15];
    const float* W1   = (const float*)d_in[16];
    const float* b1   = (const float*)d_in[17];
    const float* bn2g = (const float*)d_in[18];
    const float* bn2b = (const float*)d_in[19];
    const float* W2   = (const float*)d_in[20];
    const float* b2   = (const float*)d_in[21];
    float* out = (float*)d_out;

    knn_kernel<<<BB*64, 256>>>(p);
    qkv_gemm<<<dim3(CC/128, ROWS/128, 3), 256>>>(x, Wq, bq, Wk, bk, Wv, bv);
    pt_main<<<ROWS, 256>>>(p, p1W, p1b, pbng, pbnb, p2W, p2b,
                           bn1g, bn1b, W1, b1, bn2g, bn2b, W2, b2, out);
}

// round 6
// speedup vs baseline: 1.9095x; 1.1361x over previous
#include <cuda_runtime.h>
#include <math.h>

#define BB 16
#define NN 512
#define CC 512
#define NS 16
#define CM 64           // CC / S
#define ROWS (BB*NN)    // 8192

typedef unsigned long long ull;

__device__ __forceinline__ void ffma2(ull &d, ull a, ull b) {
    asm("fma.rn.f32x2 %0, %1, %2, %0;" : "+l"(d) : "l"(a), "l"(b));
}
__device__ __forceinline__ ull pack2(float lo, float hi) {
    ull r; asm("mov.b64 %0, {%1, %2};" : "=l"(r) : "f"(lo), "f"(hi)); return r;
}
__device__ __forceinline__ void unpack2(float &lo, float &hi, ull v) {
    asm("mov.b64 {%0, %1}, %2;" : "=f"(lo), "=f"(hi) : "l"(v));
}

// ---------------- scratch (static device globals; no allocation) -------------
__device__ float g_xq[ROWS*CC];
__device__ float g_xk[ROWS*CC];
__device__ float g_xv[ROWS*CC];
__device__ int   g_idx[ROWS*NS];

// ============================ kNN kernel =====================================
__global__ __launch_bounds__(256) void knn_kernel(const float* __restrict__ p)
{
    __shared__ float ps[NN*3];
    __shared__ float sq[NN];
    const int b    = blockIdx.x >> 6;
    const int warp = threadIdx.x >> 5;
    const int lane = threadIdx.x & 31;
    const float* pb = p + (size_t)b * NN * 3;
    for (int i = threadIdx.x; i < NN*3; i += 256) ps[i] = pb[i];
    __syncthreads();
    for (int i = threadIdx.x; i < NN; i += 256) {
        float m0 = __fmul_rn(ps[i*3+0], ps[i*3+0]);
        float m1 = __fmul_rn(ps[i*3+1], ps[i*3+1]);
        float m2 = __fmul_rn(ps[i*3+2], ps[i*3+2]);
        sq[i] = __fadd_rn(__fadd_rn(m0, m1), m2);
    }
    __syncthreads();

    const int n = (blockIdx.x & 63) * 8 + warp;
    const float px = ps[n*3+0], py = ps[n*3+1], pz = ps[n*3+2];
    const float sn = sq[n];

    float d[16];
#pragma unroll
    for (int i = 0; i < 16; i++) {
        int m = lane * 16 + i;
        float dot = __fmul_rn(px, ps[m*3+0]);
        dot = fmaf(py, ps[m*3+1], dot);
        dot = fmaf(pz, ps[m*3+2], dot);
        d[i] = __fsub_rn(__fadd_rn(sn, sq[m]), __fmul_rn(2.0f, dot));
    }

    const int row = b*NN + n;
    const float INF = __int_as_float(0x7f800000);
#pragma unroll 1
    for (int t = 0; t < NS; t++) {
        float bd = d[0]; int bi = 0;
#pragma unroll
        for (int i = 1; i < 16; i++) if (d[i] < bd) { bd = d[i]; bi = i; }
        int ib = __float_as_int(bd);
        unsigned u = (unsigned)ib ^ ((ib < 0) ? 0xFFFFFFFFu : 0x80000000u);
        ull key = ((ull)u << 32) | (unsigned)(lane*16 + bi);
#pragma unroll
        for (int s = 16; s > 0; s >>= 1) {
            ull o = __shfl_xor_sync(0xFFFFFFFFu, key, s);
            if (o < key) key = o;
        }
        int win_m = (int)(key & 0xFFFFFFFFu);
        if ((win_m >> 4) == lane) {
            int wi = win_m & 15;
#pragma unroll
            for (int i = 0; i < 16; i++) if (i == wi) d[i] = INF;
        }
        if (lane == 0) g_idx[row*NS + t] = win_m;
    }
}

// ============================ QKV GEMM =======================================
__global__ __launch_bounds__(256) void qkv_gemm(
    const float* __restrict__ x,
    const float* __restrict__ Wq, const float* __restrict__ bq,
    const float* __restrict__ Wk, const float* __restrict__ bk,
    const float* __restrict__ Wv, const float* __restrict__ bv)
{
    const float* W; const float* bias; float* out;
    if (blockIdx.z == 0)      { W = Wq; bias = bq; out = g_xq; }
    else if (blockIdx.z == 1) { W = Wk; bias = bk; out = g_xk; }
    else                      { W = Wv; bias = bv; out = g_xv; }

    __shared__ __align__(16) float As[16][132];
    __shared__ __align__(16) float Bs[16][132];

    const int tid = threadIdx.x;
    const int tx = tid & 15;
    const int ty = tid >> 4;
    const int m0 = blockIdx.y * 128;
    const int c0 = blockIdx.x * 128;
    const int b  = m0 >> 9;
    const int n0 = m0 & 511;
    const float* xb = x + (size_t)b * CC * NN;

    ull acc[8][4];
#pragma unroll
    for (int i = 0; i < 8; i++)
#pragma unroll
        for (int j = 0; j < 4; j++) acc[i][j] = 0ULL;

    for (int k0 = 0; k0 < CC; k0 += 16) {
#pragma unroll
        for (int i = 0; i < 2; i++) {
            int f  = tid + i*256;
            int kk = f >> 5;
            int mm = (f & 31) * 4;
            *reinterpret_cast<float4*>(&As[kk][mm]) =
                *reinterpret_cast<const float4*>(&xb[(size_t)(k0+kk)*NN + n0 + mm]);
            *reinterpret_cast<float4*>(&Bs[kk][mm]) =
                *reinterpret_cast<const float4*>(&W[(size_t)(k0+kk)*CC + c0 + mm]);
        }
        __syncthreads();
#pragma unroll
        for (int kk = 0; kk < 16; kk++) {
            float4 a0 = *reinterpret_cast<const float4*>(&As[kk][ty*4]);
            float4 a1 = *reinterpret_cast<const float4*>(&As[kk][64 + ty*4]);
            ulonglong2 bp01 = *reinterpret_cast<const ulonglong2*>(&Bs[kk][tx*4]);
            ulonglong2 bp23 = *reinterpret_cast<const ulonglong2*>(&Bs[kk][64 + tx*4]);
            float av[8] = {a0.x,a0.y,a0.z,a0.w, a1.x,a1.y,a1.z,a1.w};
#pragma unroll
            for (int i = 0; i < 8; i++) {
                ull ad = pack2(av[i], av[i]);
                ffma2(acc[i][0], ad, bp01.x);
                ffma2(acc[i][1], ad, bp01.y);
                ffma2(acc[i][2], ad, bp23.x);
                ffma2(acc[i][3], ad, bp23.y);
            }
        }
        __syncthreads();
    }

#pragma unroll
    for (int i = 0; i < 8; i++) {
        int row = m0 + ((i < 4) ? (ty*4 + i) : (64 + ty*4 + i - 4));
#pragma unroll
        for (int jh = 0; jh < 2; jh++) {
            int c = c0 + ((jh == 0) ? (tx*4) : (64 + tx*4));
            float e0,e1,e2,e3;
            unpack2(e0, e1, acc[i][jh*2+0]);
            unpack2(e2, e3, acc[i][jh*2+1]);
            float4 v;
            v.x = e0 + bias[c+0];
            v.y = e1 + bias[c+1];
            v.z = e2 + bias[c+2];
            v.w = e3 + bias[c+3];
            *reinterpret_cast<float4*>(&out[(size_t)row*CC + c]) = v;
        }
    }
}

// ============================ main fused kernel ==============================
// 4 points per block, 2048 blocks, 256 threads. W1/W2 staged via smem.
// Dynamic smem layout (floats):
//   aS   [0, 8448)    : 64 rows x 132  (a-chunk; later GEMM1 partials s0/s1,
//                       then a2 (64x68=4352) and y2 at [4352,8448))
//   wS   [8448,17152) : 128 x 68       (W1 chunk; later partials s2/s3, then W2)
//   xqS  [17152,19200): 4 x 512
//   bn1s [19200,19712), bn1o [19712,20224)
//   hS   [20224,20416): 64 x 3
//   idxS [20416,20480): 64 ints
#define SM_AS   0
#define SM_WS   8448
#define SM_XQ   17152
#define SM_B1S  19200
#define SM_B1O  19712
#define SM_H    20224
#define SM_IDX  20416
#define SM_TOT  20480   // floats -> 81920 bytes

__global__ __launch_bounds__(256, 2) void pt_main(
    const float* __restrict__ p,
    const float* __restrict__ p1W,  const float* __restrict__ p1b,
    const float* __restrict__ pbng, const float* __restrict__ pbnb,
    const float* __restrict__ p2W,  const float* __restrict__ p2b,
    const float* __restrict__ bn1g, const float* __restrict__ bn1bv,
    const float* __restrict__ W1,   const float* __restrict__ b1,
    const float* __restrict__ bn2g, const float* __restrict__ bn2bv,
    const float* __restrict__ W2,   const float* __restrict__ b2,
    float* __restrict__ out)
{
    extern __shared__ __align__(16) float sm[];
    float* aS   = sm + SM_AS;
    float* wS   = sm + SM_WS;
    float* xqS  = sm + SM_XQ;
    float* b1sS = sm + SM_B1S;
    float* b1oS = sm + SM_B1O;
    float* hS   = sm + SM_H;
    int*   idxS = (int*)(sm + SM_IDX);

    const int tid  = threadIdx.x;
    const int row0 = blockIdx.x * 4;        // first of 4 points
    const int b    = row0 >> 9;
    const float RS = rsqrtf(1.0f + 1e-5f);

    // ---- prologue: idx + h for 64 neighbors, xq rows, bn1 coeffs ----
    if (tid < 64) {
        int pt = tid >> 4;
        int row = row0 + pt;
        int m = g_idx[row*NS + (tid & 15)];
        idxS[tid] = m;
        int gm = b*NN + m;
        float prx = p[gm*3+0] - p[row*3+0];
        float pry = p[gm*3+1] - p[row*3+1];
        float prz = p[gm*3+2] - p[row*3+2];
#pragma unroll
        for (int j = 0; j < 3; j++) {
            float v = prx*p1W[0*3+j] + pry*p1W[1*3+j] + prz*p1W[2*3+j] + p1b[j];
            v = v * (pbng[j] * RS) + pbnb[j];
            hS[tid*3+j] = fmaxf(v, 0.0f);
        }
    }
#pragma unroll
    for (int i = 0; i < 2; i++) {
        int s = tid + i*256;                 // 512 float4 slots
        int pt = s >> 7, c4 = (s & 127) * 4;
        *reinterpret_cast<float4*>(&xqS[pt*512 + c4]) =
            *reinterpret_cast<const float4*>(&g_xq[(size_t)(row0+pt)*CC + c4]);
    }
#pragma unroll
    for (int i = 0; i < 2; i++) {
        int c = tid + i*256;
        b1sS[c] = bn1g[c] * RS;
        b1oS[c] = bn1bv[c];
    }
    __syncthreads();

    // GEMM1 thread mapping: cg(8c) x jg(2 of 8j) x pt(4) x ks(4 of 32k)
    const int cg = tid & 7;
    const int jg = (tid >> 3) & 1;
    const int pt = (tid >> 4) & 3;
    const int ks = tid >> 6;

    ull acc[8][4];
#pragma unroll
    for (int j = 0; j < 8; j++)
#pragma unroll
        for (int cp = 0; cp < 4; cp++) acc[j][cp] = 0ULL;

    for (int kc = 0; kc < 4; kc++) {
        // ---- stage W1 chunk: wS[k][c], stride 68 ----
#pragma unroll
        for (int i = 0; i < 8; i++) {
            int s = tid + i*256;             // 2048 float4 slots
            int k = s >> 4, c4 = (s & 15) * 4;
            *reinterpret_cast<float4*>(&wS[k*68 + c4]) =
                *reinterpret_cast<const float4*>(&W1[(size_t)(kc*128 + k)*CM + c4]);
        }
        // ---- phase B chunk: aS[r][k] = relu(bn1(xk - xq + pr)), r=pt*16+j ----
#pragma unroll
        for (int i = 0; i < 8; i++) {
            int s = tid + i*256;             // 2048 float4 slots
            int r = s >> 5, k4 = (s & 31) * 4;
            int c = kc*128 + k4;
            int ptb = r >> 4;
            int m  = idxS[r];
            float h0 = hS[r*3+0], h1 = hS[r*3+1], h2 = hS[r*3+2];
            float4 xk4 = *reinterpret_cast<const float4*>(&g_xk[(size_t)(b*NN+m)*CC + c]);
            float4 q04 = *reinterpret_cast<const float4*>(&p2W[c]);
            float4 q14 = *reinterpret_cast<const float4*>(&p2W[CC + c]);
            float4 q24 = *reinterpret_cast<const float4*>(&p2W[2*CC + c]);
            float4 pb4 = *reinterpret_cast<const float4*>(&p2b[c]);
            float4 xq4 = *reinterpret_cast<const float4*>(&xqS[ptb*512 + c]);
            float4 s14 = *reinterpret_cast<const float4*>(&b1sS[c]);
            float4 o14 = *reinterpret_cast<const float4*>(&b1oS[c]);
            float4 res;
            {
                float pr = h0*q04.x + h1*q14.x + h2*q24.x + pb4.x;
                res.x = fmaxf(fmaf(xk4.x - xq4.x + pr, s14.x, o14.x), 0.0f);
                pr = h0*q04.y + h1*q14.y + h2*q24.y + pb4.y;
                res.y = fmaxf(fmaf(xk4.y - xq4.y + pr, s14.y, o14.y), 0.0f);
                pr = h0*q04.z + h1*q14.z + h2*q24.z + pb4.z;
                res.z = fmaxf(fmaf(xk4.z - xq4.z + pr, s14.z, o14.z), 0.0f);
                pr = h0*q04.w + h1*q14.w + h2*q24.w + pb4.w;
                res.w = fmaxf(fmaf(xk4.w - xq4.w + pr, s14.w, o14.w), 0.0f);
            }
            *reinterpret_cast<float4*>(&aS[r*132 + k4]) = res;
        }
        __syncthreads();

        // ---- GEMM1 chunk: acc += a(8j x 32k) @ W1chunk(32k x 8c) ----
        {
            const float* aB = aS + (pt*16 + jg*8)*132 + ks*32;
            const float* wB = wS + (ks*32)*68 + cg*8;
#pragma unroll 2
            for (int k4 = 0; k4 < 32; k4 += 4) {
                float4 av[8];
#pragma unroll
                for (int j = 0; j < 8; j++)
                    av[j] = *reinterpret_cast<const float4*>(aB + j*132 + k4);
#pragma unroll
                for (int kk = 0; kk < 4; kk++) {
                    const float* wrow = wB + (k4+kk)*68;
                    ulonglong2 w01 = *reinterpret_cast<const ulonglong2*>(wrow);
                    ulonglong2 w23 = *reinterpret_cast<const ulonglong2*>(wrow + 4);
#pragma unroll
                    for (int j = 0; j < 8; j++) {
                        const float* af = (const float*)&av[j];
                        float a = af[kk];
                        ull ad = pack2(a, a);
                        ffma2(acc[j][0], ad, w01.x);
                        ffma2(acc[j][1], ad, w01.y);
                        ffma2(acc[j][2], ad, w23.x);
                        ffma2(acc[j][3], ad, w23.y);
                    }
                }
            }
        }
        __syncthreads();
    }

    // ---- spill partials: ks 0/1 -> aS, ks 2/3 -> wS ----
    {
        float* dst = ((ks < 2) ? aS : wS) + (ks & 1) * 4096;
        int base = pt*1024 + jg*8*64 + cg*8;
#pragma unroll
        for (int j = 0; j < 8; j++) {
#pragma unroll
            for (int cp = 0; cp < 4; cp++) {
                float lo, hi;
                unpack2(lo, hi, acc[j][cp]);
                *reinterpret_cast<float2*>(&dst[base + j*64 + cp*2]) =
                    make_float2(lo, hi);
            }
        }
    }
    __syncthreads();

    // ---- reduce 4 slices + bias + bn2 + relu -> regs ----
    float a2v[16];
#pragma unroll
    for (int i = 0; i < 16; i++) {
        int o = tid + i*256;
        int c = o & 63;
        float s = aS[o] + aS[4096 + o] + wS[o] + wS[4096 + o];
        s += b1[c];
        s = fmaf(s, bn2g[c]*RS, bn2bv[c]);
        a2v[i] = fmaxf(s, 0.0f);
    }
    __syncthreads();

    // ---- write a2 (stride 68 rows in aS) + stage W2 into wS ----
#pragma unroll
    for (int i = 0; i < 16; i++) {
        int o = tid + i*256;
        int r = o >> 6, c = o & 63;
        aS[r*68 + c] = a2v[i];
    }
#pragma unroll
    for (int i = 0; i < 4; i++) {
        int s = tid + i*256;                 // 1024 float4 slots
        int k = s >> 4, c4 = (s & 15) * 4;
        *reinterpret_cast<float4*>(&wS[k*68 + c4]) =
            *reinterpret_cast<const float4*>(&W2[(size_t)k*CM + c4]);
    }
    __syncthreads();

    // ---- GEMM2: (64 rows x 64k) @ (64k x 64c); 128 threads ----
    if (tid < 128) {
        const int cg2 = tid & 7;
        const int jg2 = (tid >> 3) & 1;
        const int pt2 = (tid >> 4) & 3;
        ull acc2[8][4];
#pragma unroll
        for (int j = 0; j < 8; j++)
#pragma unroll
            for (int cp = 0; cp < 4; cp++) acc2[j][cp] = 0ULL;

        const float* aB = aS + (pt2*16 + jg2*8)*68;
        const float* wB = wS + cg2*8;
#pragma unroll 2
        for (int k4 = 0; k4 < 64; k4 += 4) {
            float4 av[8];
#pragma unroll
            for (int j = 0; j < 8; j++)
                av[j] = *reinterpret_cast<const float4*>(aB + j*68 + k4);
#pragma unroll
            for (int kk = 0; kk < 4; kk++) {
                const float* wrow = wB + (k4+kk)*68;
                ulonglong2 w01 = *reinterpret_cast<const ulonglong2*>(wrow);
                ulonglong2 w23 = *reinterpret_cast<const ulonglong2*>(wrow + 4);
#pragma unroll
                for (int j = 0; j < 8; j++) {
                    const float* af = (const float*)&av[j];
                    float a = af[kk];
                    ull ad = pack2(a, a);
                    ffma2(acc2[j][0], ad, w01.x);
                    ffma2(acc2[j][1], ad, w01.y);
                    ffma2(acc2[j][2], ad, w23.x);
                    ffma2(acc2[j][3], ad, w23.y);
                }
            }
        }
        float* y2 = aS + 4352;
        int base = pt2*1024 + jg2*8*64 + cg2*8;
#pragma unroll
        for (int j = 0; j < 8; j++) {
#pragma unroll
            for (int cp = 0; cp < 4; cp++) {
                float lo, hi;
                unpack2(lo, hi, acc2[j][cp]);
                int c = cg2*8 + cp*2;
                *reinterpret_cast<float2*>(&y2[base + j*64 + cp*2]) =
                    make_float2(lo + b2[c], hi + b2[c+1]);
            }
        }
    }
    __syncthreads();

    // ---- softmax over 16 neighbors per (pt, c) ----
    {
        float* y2 = aS + 4352;
        int ptc = tid >> 6;
        int c   = tid & 63;
        float* col = y2 + ptc*1024 + c;
        float mx = -3.4e38f;
#pragma unroll
        for (int j = 0; j < NS; j++) mx = fmaxf(mx, col[j*64]);
        float ex[NS];
        float sum = 0.0f;
#pragma unroll
        for (int j = 0; j < NS; j++) {
            ex[j] = expf(col[j*64] - mx);
            sum += ex[j];
        }
        float inv = 1.0f / sum;
#pragma unroll
        for (int j = 0; j < NS; j++) col[j*64] = ex[j] * inv;
    }
    __syncthreads();

    // ---- epilogue: out[pt][cf] = sum_j (xv[m]+pr) * w[j][cf&63] ----
    {
        const float* y2 = aS + 4352;
#pragma unroll
        for (int i = 0; i < 8; i++) {
            int s = tid + i*256;             // 2048 outputs
            int ptb = s >> 9, cf = s & 511;
            int cc = cf & 63;
            float q0 = p2W[cf], q1 = p2W[CC+cf], q2 = p2W[2*CC+cf], qb = p2b[cf];
            const float* wcol = y2 + ptb*1024 + cc;
            const int* idxp = idxS + ptb*16;
            const float* hp = hS + ptb*48;
            float acco = 0.0f;
#pragma unroll
            for (int j = 0; j < NS; j++) {
                int m = idxp[j];
                float pr = hp[j*3+0]*q0 + hp[j*3+1]*q1 + hp[j*3+2]*q2 + qb;
                float v  = g_xv[(size_t)(b*NN+m)*CC + cf] + pr;
                acco = fmaf(v, wcol[j*64], acco);
            }
            out[(size_t)(row0+ptb)*CC + cf] = acco;
        }
    }
}

// ============================ launcher =======================================
extern "C" void kernel_launch(void* const* d_in, const int* in_sizes, int n_in,
                              void* d_out, int out_size)
{
    const float* p    = (const float*)d_in[0];
    const float* x    = (const float*)d_in[1];
    const float* Wq   = (const float*)d_in[2];
    const float* bq   = (const float*)d_in[3];
    const float* Wk   = (const float*)d_in[4];
    const float* bk   = (const float*)d_in[5];
    const float* Wv   = (const float*)d_in[6];
    const float* bv   = (const float*)d_in[7];
    const float* p1W  = (const float*)d_in[8];
    const float* p1b  = (const float*)d_in[9];
    const float* pbng = (const float*)d_in[10];
    const float* pbnb = (const float*)d_in[11];
    const float* p2W  = (const float*)d_in[12];
    const float* p2b  = (const float*)d_in[13];
    const float* bn1g = (const float*)d_in[14];
    const float* bn1b = (const float*)d_in[15];
    const float* W1   = (const float*)d_in[16];
    const float* b1   = (const float*)d_in[17];
    const float* bn2g = (const float*)d_in[18];
    const float* bn2b = (const float*)d_in[19];
    const float* W2   = (const float*)d_in[20];
    const float* b2   = (const float*)d_in[21];
    float* out = (float*)d_out;

    cudaFuncSetAttribute(pt_main, cudaFuncAttributeMaxDynamicSharedMemorySize,
                         SM_TOT * sizeof(float));

    knn_kernel<<<BB*64, 256>>>(p);
    qkv_gemm<<<dim3(CC/128, ROWS/128, 3), 256>>>(x, Wq, bq, Wk, bk, Wv, bv);
    pt_main<<<ROWS/4, 256, SM_TOT * sizeof(float)>>>(
        p, p1W, p1b, pbng, pbnb, p2W, p2b,
        bn1g, bn1b, W1, b1, bn2g, bn2b, W2, b2, out);
}

// round 7
// speedup vs baseline: 1.9354x; 1.0135x over previous
#include <cuda_runtime.h>
#include <math.h>

#define BB 16
#define NN 512
#define CC 512
#define NS 16
#define CM 64           // CC / S
#define ROWS (BB*NN)    // 8192

typedef unsigned long long ull;

__device__ __forceinline__ void ffma2(ull &d, ull a, ull b) {
    asm("fma.rn.f32x2 %0, %1, %2, %0;" : "+l"(d) : "l"(a), "l"(b));
}
__device__ __forceinline__ ull pack2(float lo, float hi) {
    ull r; asm("mov.b64 %0, {%1, %2};" : "=l"(r) : "f"(lo), "f"(hi)); return r;
}
__device__ __forceinline__ void unpack2(float &lo, float &hi, ull v) {
    asm("mov.b64 {%0, %1}, %2;" : "=f"(lo), "=f"(hi) : "l"(v));
}

// ---------------- scratch (static device globals; no allocation) -------------
__device__ float g_xq[ROWS*CC];
__device__ float g_xk[ROWS*CC];
__device__ float g_xv[ROWS*CC];
__device__ int   g_idx[ROWS*NS];

// ================= stage1: fused QKV GEMM + kNN in one launch ================
// Blocks [0, 768): qkv tiles (z = bid/256 selects q/k/v, tile = bid%256).
// Blocks [768, 1792): kNN (1024 blocks, 8 warps = 8 queries each).
// knn blocks are scheduled after the qkv tiles and fill the partial waves.
#define QKV_BLOCKS 768

__global__ __launch_bounds__(256) void stage1_kernel(
    const float* __restrict__ p,
    const float* __restrict__ x,
    const float* __restrict__ Wq, const float* __restrict__ bq,
    const float* __restrict__ Wk, const float* __restrict__ bk,
    const float* __restrict__ Wv, const float* __restrict__ bv)
{
    __shared__ __align__(16) float smem_u[2 * 16 * 132];   // 16.9 KB union

    if (blockIdx.x < QKV_BLOCKS) {
        // ---------------- QKV GEMM: 128x128 tile, BK=16, FFMA2 ----------------
        float (*As)[132] = reinterpret_cast<float(*)[132]>(smem_u);
        float (*Bs)[132] = reinterpret_cast<float(*)[132]>(smem_u + 16*132);

        const int z    = blockIdx.x >> 8;          // 0,1,2
        const int tile = blockIdx.x & 255;
        const float* W; const float* bias; float* out;
        if (z == 0)      { W = Wq; bias = bq; out = g_xq; }
        else if (z == 1) { W = Wk; bias = bk; out = g_xk; }
        else             { W = Wv; bias = bv; out = g_xv; }

        const int tid = threadIdx.x;
        const int tx = tid & 15;
        const int ty = tid >> 4;
        const int m0 = (tile >> 2) * 128;          // 64 m-tiles
        const int c0 = (tile & 3) * 128;           // 4 c-tiles
        const int b  = m0 >> 9;
        const int n0 = m0 & 511;
        const float* xb = x + (size_t)b * CC * NN;

        ull acc[8][4];
#pragma unroll
        for (int i = 0; i < 8; i++)
#pragma unroll
            for (int j = 0; j < 4; j++) acc[i][j] = 0ULL;

        for (int k0 = 0; k0 < CC; k0 += 16) {
#pragma unroll
            for (int i = 0; i < 2; i++) {
                int f  = tid + i*256;
                int kk = f >> 5;
                int mm = (f & 31) * 4;
                *reinterpret_cast<float4*>(&As[kk][mm]) =
                    *reinterpret_cast<const float4*>(&xb[(size_t)(k0+kk)*NN + n0 + mm]);
                *reinterpret_cast<float4*>(&Bs[kk][mm]) =
                    *reinterpret_cast<const float4*>(&W[(size_t)(k0+kk)*CC + c0 + mm]);
            }
            __syncthreads();
#pragma unroll
            for (int kk = 0; kk < 16; kk++) {
                float4 a0 = *reinterpret_cast<const float4*>(&As[kk][ty*4]);
                float4 a1 = *reinterpret_cast<const float4*>(&As[kk][64 + ty*4]);
                ulonglong2 bp01 = *reinterpret_cast<const ulonglong2*>(&Bs[kk][tx*4]);
                ulonglong2 bp23 = *reinterpret_cast<const ulonglong2*>(&Bs[kk][64 + tx*4]);
                float av[8] = {a0.x,a0.y,a0.z,a0.w, a1.x,a1.y,a1.z,a1.w};
#pragma unroll
                for (int i = 0; i < 8; i++) {
                    ull ad = pack2(av[i], av[i]);
                    ffma2(acc[i][0], ad, bp01.x);
                    ffma2(acc[i][1], ad, bp01.y);
                    ffma2(acc[i][2], ad, bp23.x);
                    ffma2(acc[i][3], ad, bp23.y);
                }
            }
            __syncthreads();
        }

#pragma unroll
        for (int i = 0; i < 8; i++) {
            int row = m0 + ((i < 4) ? (ty*4 + i) : (64 + ty*4 + i - 4));
#pragma unroll
            for (int jh = 0; jh < 2; jh++) {
                int c = c0 + ((jh == 0) ? (tx*4) : (64 + tx*4));
                float e0,e1,e2,e3;
                unpack2(e0, e1, acc[i][jh*2+0]);
                unpack2(e2, e3, acc[i][jh*2+1]);
                float4 v;
                v.x = e0 + bias[c+0];
                v.y = e1 + bias[c+1];
                v.z = e2 + bias[c+2];
                v.w = e3 + bias[c+3];
                *reinterpret_cast<float4*>(&out[(size_t)row*CC + c]) = v;
            }
        }
    } else {
        // ---------------- kNN: warp per query; ulp-exact distances ------------
        float* ps = smem_u;            // NN*3 floats
        float* sq = smem_u + NN*3;     // NN floats
        const int kb   = blockIdx.x - QKV_BLOCKS;
        const int b    = kb >> 6;
        const int warp = threadIdx.x >> 5;
        const int lane = threadIdx.x & 31;
        const float* pb = p + (size_t)b * NN * 3;
        for (int i = threadIdx.x; i < NN*3; i += 256) ps[i] = pb[i];
        __syncthreads();
        for (int i = threadIdx.x; i < NN; i += 256) {
            float m0 = __fmul_rn(ps[i*3+0], ps[i*3+0]);
            float m1 = __fmul_rn(ps[i*3+1], ps[i*3+1]);
            float m2 = __fmul_rn(ps[i*3+2], ps[i*3+2]);
            sq[i] = __fadd_rn(__fadd_rn(m0, m1), m2);
        }
        __syncthreads();

        const int n = (kb & 63) * 8 + warp;
        const float px = ps[n*3+0], py = ps[n*3+1], pz = ps[n*3+2];
        const float sn = sq[n];

        float d[16];
#pragma unroll
        for (int i = 0; i < 16; i++) {
            int m = lane * 16 + i;
            float dot = __fmul_rn(px, ps[m*3+0]);
            dot = fmaf(py, ps[m*3+1], dot);
            dot = fmaf(pz, ps[m*3+2], dot);
            d[i] = __fsub_rn(__fadd_rn(sn, sq[m]), __fmul_rn(2.0f, dot));
        }

        const int row = b*NN + n;
        const float INF = __int_as_float(0x7f800000);
#pragma unroll 1
        for (int t = 0; t < NS; t++) {
            float bd = d[0]; int bi = 0;
#pragma unroll
            for (int i = 1; i < 16; i++) if (d[i] < bd) { bd = d[i]; bi = i; }
            int ib = __float_as_int(bd);
            unsigned u = (unsigned)ib ^ ((ib < 0) ? 0xFFFFFFFFu : 0x80000000u);
            ull key = ((ull)u << 32) | (unsigned)(lane*16 + bi);
#pragma unroll
            for (int s = 16; s > 0; s >>= 1) {
                ull o = __shfl_xor_sync(0xFFFFFFFFu, key, s);
                if (o < key) key = o;
            }
            int win_m = (int)(key & 0xFFFFFFFFu);
            if ((win_m >> 4) == lane) {
                int wi = win_m & 15;
#pragma unroll
                for (int i = 0; i < 16; i++) if (i == wi) d[i] = INF;
            }
            if (lane == 0) g_idx[row*NS + t] = win_m;
        }
    }
}

// ============================ main fused kernel ==============================
// 4 points per block, 2048 blocks, 256 threads. W1/W2 staged via smem.
#define SM_AS   0
#define SM_WS   8448
#define SM_XQ   17152
#define SM_B1S  19200
#define SM_B1O  19712
#define SM_H    20224
#define SM_IDX  20416
#define SM_TOT  20480   // floats -> 81920 bytes

__global__ __launch_bounds__(256, 2) void pt_main(
    const float* __restrict__ p,
    const float* __restrict__ p1W,  const float* __restrict__ p1b,
    const float* __restrict__ pbng, const float* __restrict__ pbnb,
    const float* __restrict__ p2W,  const float* __restrict__ p2b,
    const float* __restrict__ bn1g, const float* __restrict__ bn1bv,
    const float* __restrict__ W1,   const float* __restrict__ b1,
    const float* __restrict__ bn2g, const float* __restrict__ bn2bv,
    const float* __restrict__ W2,   const float* __restrict__ b2,
    float* __restrict__ out)
{
    extern __shared__ __align__(16) float sm[];
    float* aS   = sm + SM_AS;
    float* wS   = sm + SM_WS;
    float* xqS  = sm + SM_XQ;
    float* b1sS = sm + SM_B1S;
    float* b1oS = sm + SM_B1O;
    float* hS   = sm + SM_H;
    int*   idxS = (int*)(sm + SM_IDX);

    const int tid  = threadIdx.x;
    const int row0 = blockIdx.x * 4;
    const int b    = row0 >> 9;
    const float RS = rsqrtf(1.0f + 1e-5f);

    // ---- prologue ----
    if (tid < 64) {
        int pt = tid >> 4;
        int row = row0 + pt;
        int m = g_idx[row*NS + (tid & 15)];
        idxS[tid] = m;
        int gm = b*NN + m;
        float prx = p[gm*3+0] - p[row*3+0];
        float pry = p[gm*3+1] - p[row*3+1];
        float prz = p[gm*3+2] - p[row*3+2];
#pragma unroll
        for (int j = 0; j < 3; j++) {
            float v = prx*p1W[0*3+j] + pry*p1W[1*3+j] + prz*p1W[2*3+j] + p1b[j];
            v = v * (pbng[j] * RS) + pbnb[j];
            hS[tid*3+j] = fmaxf(v, 0.0f);
        }
    }
#pragma unroll
    for (int i = 0; i < 2; i++) {
        int s = tid + i*256;
        int pt = s >> 7, c4 = (s & 127) * 4;
        *reinterpret_cast<float4*>(&xqS[pt*512 + c4]) =
            *reinterpret_cast<const float4*>(&g_xq[(size_t)(row0+pt)*CC + c4]);
    }
#pragma unroll
    for (int i = 0; i < 2; i++) {
        int c = tid + i*256;
        b1sS[c] = bn1g[c] * RS;
        b1oS[c] = bn1bv[c];
    }
    __syncthreads();

    // GEMM1 mapping: cg(8c) x jg(2 of 8j) x pt(4) x ks(4 of 32k)
    const int cg = tid & 7;
    const int jg = (tid >> 3) & 1;
    const int pt = (tid >> 4) & 3;
    const int ks = tid >> 6;

    ull acc[8][4];
#pragma unroll
    for (int j = 0; j < 8; j++)
#pragma unroll
        for (int cp = 0; cp < 4; cp++) acc[j][cp] = 0ULL;

    for (int kc = 0; kc < 4; kc++) {
        // stage W1 chunk: wS[k][c], stride 68
#pragma unroll
        for (int i = 0; i < 8; i++) {
            int s = tid + i*256;
            int k = s >> 4, c4 = (s & 15) * 4;
            *reinterpret_cast<float4*>(&wS[k*68 + c4]) =
                *reinterpret_cast<const float4*>(&W1[(size_t)(kc*128 + k)*CM + c4]);
        }
        // phase B chunk: aS[r][k] = relu(bn1(xk - xq + pr))
#pragma unroll
        for (int i = 0; i < 8; i++) {
            int s = tid + i*256;
            int r = s >> 5, k4 = (s & 31) * 4;
            int c = kc*128 + k4;
            int ptb = r >> 4;
            int m  = idxS[r];
            float h0 = hS[r*3+0], h1 = hS[r*3+1], h2 = hS[r*3+2];
            float4 xk4 = *reinterpret_cast<const float4*>(&g_xk[(size_t)(b*NN+m)*CC + c]);
            float4 q04 = *reinterpret_cast<const float4*>(&p2W[c]);
            float4 q14 = *reinterpret_cast<const float4*>(&p2W[CC + c]);
            float4 q24 = *reinterpret_cast<const float4*>(&p2W[2*CC + c]);
            float4 pb4 = *reinterpret_cast<const float4*>(&p2b[c]);
            float4 xq4 = *reinterpret_cast<const float4*>(&xqS[ptb*512 + c]);
            float4 s14 = *reinterpret_cast<const float4*>(&b1sS[c]);
            float4 o14 = *reinterpret_cast<const float4*>(&b1oS[c]);
            float4 res;
            {
                float pr = h0*q04.x + h1*q14.x + h2*q24.x + pb4.x;
                res.x = fmaxf(fmaf(xk4.x - xq4.x + pr, s14.x, o14.x), 0.0f);
                pr = h0*q04.y + h1*q14.y + h2*q24.y + pb4.y;
                res.y = fmaxf(fmaf(xk4.y - xq4.y + pr, s14.y, o14.y), 0.0f);
                pr = h0*q04.z + h1*q14.z + h2*q24.z + pb4.z;
                res.z = fmaxf(fmaf(xk4.z - xq4.z + pr, s14.z, o14.z), 0.0f);
                pr = h0*q04.w + h1*q14.w + h2*q24.w + pb4.w;
                res.w = fmaxf(fmaf(xk4.w - xq4.w + pr, s14.w, o14.w), 0.0f);
            }
            *reinterpret_cast<float4*>(&aS[r*132 + k4]) = res;
        }
        __syncthreads();

        // GEMM1 chunk
        {
            const float* aB = aS + (pt*16 + jg*8)*132 + ks*32;
            const float* wB = wS + (ks*32)*68 + cg*8;
#pragma unroll 2
            for (int k4 = 0; k4 < 32; k4 += 4) {
                float4 av[8];
#pragma unroll
                for (int j = 0; j < 8; j++)
                    av[j] = *reinterpret_cast<const float4*>(aB + j*132 + k4);
#pragma unroll
                for (int kk = 0; kk < 4; kk++) {
                    const float* wrow = wB + (k4+kk)*68;
                    ulonglong2 w01 = *reinterpret_cast<const ulonglong2*>(wrow);
                    ulonglong2 w23 = *reinterpret_cast<const ulonglong2*>(wrow + 4);
#pragma unroll
                    for (int j = 0; j < 8; j++) {
                        const float* af = (const float*)&av[j];
                        float a = af[kk];
                        ull ad = pack2(a, a);
                        ffma2(acc[j][0], ad, w01.x);
                        ffma2(acc[j][1], ad, w01.y);
                        ffma2(acc[j][2], ad, w23.x);
                        ffma2(acc[j][3], ad, w23.y);
                    }
                }
            }
        }
        __syncthreads();
    }

    // spill partials: ks 0/1 -> aS, ks 2/3 -> wS
    {
        float* dst = ((ks < 2) ? aS : wS) + (ks & 1) * 4096;
        int base = pt*1024 + jg*8*64 + cg*8;
#pragma unroll
        for (int j = 0; j < 8; j++) {
#pragma unroll
            for (int cp = 0; cp < 4; cp++) {
                float lo, hi;
                unpack2(lo, hi, acc[j][cp]);
                *reinterpret_cast<float2*>(&dst[base + j*64 + cp*2]) =
                    make_float2(lo, hi);
            }
        }
    }
    __syncthreads();

    // reduce 4 slices + bias + bn2 + relu
    float a2v[16];
#pragma unroll
    for (int i = 0; i < 16; i++) {
        int o = tid + i*256;
        int c = o & 63;
        float s = aS[o] + aS[4096 + o] + wS[o] + wS[4096 + o];
        s += b1[c];
        s = fmaf(s, bn2g[c]*RS, bn2bv[c]);
        a2v[i] = fmaxf(s, 0.0f);
    }
    __syncthreads();

    // write a2 (stride 68) + stage W2
#pragma unroll
    for (int i = 0; i < 16; i++) {
        int o = tid + i*256;
        int r = o >> 6, c = o & 63;
        aS[r*68 + c] = a2v[i];
    }
#pragma unroll
    for (int i = 0; i < 4; i++) {
        int s = tid + i*256;
        int k = s >> 4, c4 = (s & 15) * 4;
        *reinterpret_cast<float4*>(&wS[k*68 + c4]) =
            *reinterpret_cast<const float4*>(&W2[(size_t)k*CM + c4]);
    }
    __syncthreads();

    // ---- GEMM2: (64 rows x 64k) @ (64k x 64c); all 256 threads, 4 rows each --
    {
        const int cg2 = tid & 7;
        const int jg2 = (tid >> 3) & 1;
        const int pt2 = (tid >> 4) & 3;
        const int jh  = tid >> 7;           // 0/1: which half of the 8 rows
        ull acc2[4][4];
#pragma unroll
        for (int j = 0; j < 4; j++)
#pragma unroll
            for (int cp = 0; cp < 4; cp++) acc2[j][cp] = 0ULL;

        const float* aB = aS + (pt2*16 + jg2*8 + jh*4)*68;
        const float* wB = wS + cg2*8;
#pragma unroll 2
        for (int k4 = 0; k4 < 64; k4 += 4) {
            float4 av[4];
#pragma unroll
            for (int j = 0; j < 4; j++)
                av[j] = *reinterpret_cast<const float4*>(aB + j*68 + k4);
#pragma unroll
            for (int kk = 0; kk < 4; kk++) {
                const float* wrow = wB + (k4+kk)*68;
                ulonglong2 w01 = *reinterpret_cast<const ulonglong2*>(wrow);
                ulonglong2 w23 = *reinterpret_cast<const ulonglong2*>(wrow + 4);
#pragma unroll
                for (int j = 0; j < 4; j++) {
                    const float* af = (const float*)&av[j];
                    float a = af[kk];
                    ull ad = pack2(a, a);
                    ffma2(acc2[j][0], ad, w01.x);
                    ffma2(acc2[j][1], ad, w01.y);
                    ffma2(acc2[j][2], ad, w23.x);
                    ffma2(acc2[j][3], ad, w23.y);
                }
            }
        }
        float* y2 = aS + 4352;
        int base = pt2*1024 + (jg2*8 + jh*4)*64 + cg2*8;
#pragma unroll
        for (int j = 0; j < 4; j++) {
#pragma unroll
            for (int cp = 0; cp < 4; cp++) {
                float lo, hi;
                unpack2(lo, hi, acc2[j][cp]);
                int c = cg2*8 + cp*2;
                *reinterpret_cast<float2*>(&y2[base + j*64 + cp*2]) =
                    make_float2(lo + b2[c], hi + b2[c+1]);
            }
        }
    }
    __syncthreads();

    // ---- softmax over 16 neighbors per (pt, c) ----
    {
        float* y2 = aS + 4352;
        int ptc = tid >> 6;
        int c   = tid & 63;
        float* col = y2 + ptc*1024 + c;
        float mx = -3.4e38f;
#pragma unroll
        for (int j = 0; j < NS; j++) mx = fmaxf(mx, col[j*64]);
        float ex[NS];
        float sum = 0.0f;
#pragma unroll
        for (int j = 0; j < NS; j++) {
            ex[j] = expf(col[j*64] - mx);
            sum += ex[j];
        }
        float inv = 1.0f / sum;
#pragma unroll
        for (int j = 0; j < NS; j++) col[j*64] = ex[j] * inv;
    }
    __syncthreads();

    // ---- epilogue ----
    {
        const float* y2 = aS + 4352;
#pragma unroll
        for (int i = 0; i < 8; i++) {
            int s = tid + i*256;
            int ptb = s >> 9, cf = s & 511;
            int cc = cf & 63;
            float q0 = p2W[cf], q1 = p2W[CC+cf], q2 = p2W[2*CC+cf], qb = p2b[cf];
            const float* wcol = y2 + ptb*1024 + cc;
            const int* idxp = idxS + ptb*16;
            const float* hp = hS + ptb*48;
            float acco = 0.0f;
#pragma unroll
            for (int j = 0; j < NS; j++) {
                int m = idxp[j];
                float pr = hp[j*3+0]*q0 + hp[j*3+1]*q1 + hp[j*3+2]*q2 + qb;
                float v  = g_xv[(size_t)(b*NN+m)*CC + cf] + pr;
                acco = fmaf(v, wcol[j*64], acco);
            }
            out[(size_t)(row0+ptb)*CC + cf] = acco;
        }
    }
}

// ============================ launcher =======================================
extern "C" void kernel_launch(void* const* d_in, const int* in_sizes, int n_in,
                              void* d_out, int out_size)
{
    const float* p    = (const float*)d_in[0];
    const float* x    = (const float*)d_in[1];
    const float* Wq   = (const float*)d_in[2];
    const float* bq   = (const float*)d_in[3];
    const float* Wk   = (const float*)d_in[4];
    const float* bk   = (const float*)d_in[5];
    const float* Wv   = (const float*)d_in[6];
    const float* bv   = (const float*)d_in[7];
    const float* p1W  = (const float*)d_in[8];
    const float* p1b  = (const float*)d_in[9];
    const float* pbng = (const float*)d_in[10];
    const float* pbnb = (const float*)d_in[11];
    const float* p2W  = (const float*)d_in[12];
    const float* p2b  = (const float*)d_in[13];
    const float* bn1g = (const float*)d_in[14];
    const float* bn1b = (const float*)d_in[15];
    const float* W1   = (const float*)d_in[16];
    const float* b1   = (const float*)d_in[17];
    const float* bn2g = (const float*)d_in[18];
    const float* bn2b = (const float*)d_in[19];
    const float* W2   = (const float*)d_in[20];
    const float* b2   = (const float*)d_in[21];
    float* out = (float*)d_out;

    cudaFuncSetAttribute(pt_main, cudaFuncAttributeMaxDynamicSharedMemorySize,
                         SM_TOT * sizeof(float));

    stage1_kernel<<<QKV_BLOCKS + BB*64, 256>>>(p, x, Wq, bq, Wk, bk, Wv, bv);
    pt_main<<<ROWS/4, 256, SM_TOT * sizeof(float)>>>(
        p, p1W, p1b, pbng, pbnb, p2W, p2b,
        bn1g, bn1b, W1, b1, bn2g, bn2b, W2, b2, out);
}